// round 8
// baseline (speedup 1.0000x reference)
#include <cuda_runtime.h>

#define F_NODES 16384
#define DEG 8
#define E (F_NODES * DEG)   // 131072
#define B 64
#define H 16
#define LAYERS 10

#define NPB 8               // nodes per block
#define TPN 16              // threads per node (4 batch elems each)

typedef unsigned long long u64;

// Scratch buffers in (E, B) transposed layout.
__device__ float g_x0T[(size_t)E * B];
__device__ float g_xA [(size_t)E * B];
__device__ float g_xB [(size_t)E * B];

__device__ __forceinline__ u64 pack2(float lo, float hi) {
    u64 r; asm("mov.b64 %0, {%1, %2};" : "=l"(r) : "f"(lo), "f"(hi)); return r;
}
__device__ __forceinline__ void unpack2(u64 v, float& lo, float& hi) {
    asm("mov.b64 {%0, %1}, %2;" : "=f"(lo), "=f"(hi) : "l"(v));
}
__device__ __forceinline__ void fma2(u64& d, u64 a, u64 b, u64 c) {
    asm("fma.rn.f32x2 %0, %1, %2, %3;" : "=l"(d) : "l"(a), "l"(b), "l"(c));
}
__device__ __forceinline__ u64 add2(u64 a, u64 b) {
    u64 r; asm("add.rn.f32x2 %0, %1, %2;" : "=l"(r) : "l"(a), "l"(b)); return r;
}
// L2 eviction-policy descriptors (createpolicy + cache_hint is the only form
// ptxas accepts at sub-256-bit widths on sm_103a).
__device__ __forceinline__ u64 mk_evict_last_policy() {
    u64 pol;
    asm("createpolicy.fractional.L2::evict_last.b64 %0, 1.0;" : "=l"(pol));
    return pol;
}
__device__ __forceinline__ u64 mk_evict_first_policy() {
    u64 pol;
    asm("createpolicy.fractional.L2::evict_first.b64 %0, 1.0;" : "=l"(pol));
    return pol;
}
// Policy-carrying loads.
__device__ __forceinline__ float4 ld_pol128(const float* p, u64 pol) {
    float4 v;
    asm("ld.global.L2::cache_hint.v4.f32 {%0,%1,%2,%3}, [%4], %5;"
        : "=f"(v.x), "=f"(v.y), "=f"(v.z), "=f"(v.w) : "l"(p), "l"(pol));
    return v;
}
__device__ __forceinline__ float ld_pol32(const float* p, u64 pol) {
    float v;
    asm("ld.global.L2::cache_hint.f32 %0, [%1], %2;" : "=f"(v) : "l"(p), "l"(pol));
    return v;
}
// Branchless ELU (alpha=1): max(x,0) + (exp(min(x,0)) - 1)
__device__ __forceinline__ float elu1(float x) {
    return fmaxf(x, 0.0f) + (__expf(fminf(x, 0.0f)) - 1.0f);
}

// Per-node smem weights.
struct __align__(16) NodeW {
    u64   sb1[16];     // b1 splats
    u64   sb2[8];      // b2 splats
    float w1[128];     // W1[j][d], j-major (raw global layout)
    float w2t[128];    // W2 transposed: w2t[j*8 + d] = W2[d][j]
    u64   pad[2];
};

// (B, E) row-major -> (E, B)
__global__ void k_transpose_in(const float* __restrict__ in, float* __restrict__ out) {
    __shared__ float t[32][33];
    int e0 = blockIdx.x * 32, b0 = blockIdx.y * 32;
    int tx = threadIdx.x, ty = threadIdx.y;
    t[ty][tx] = in[(size_t)(b0 + ty) * E + e0 + tx];
    __syncthreads();
    out[(size_t)(e0 + ty) * B + b0 + tx] = t[tx][ty];
}

// One GSNN layer in (E, B) space. 16 threads/node, 4 batch elems/thread.
// final==0: dst is (E,B) ping-pong (default stores; next layer reads them).
// final==1: dst is the (B,E) output; transpose done in registers.
__global__ __launch_bounds__(NPB * TPN)
void layer_kernel(const float* __restrict__ src, float* __restrict__ dst,
                  const float* __restrict__ W1, const float* __restrict__ b1,
                  const float* __restrict__ W2, const float* __restrict__ b2,
                  const int* __restrict__ in_ixs, const float* __restrict__ x0T,
                  int final_flag) {
    __shared__ NodeW sw[NPB];
    const int tid  = threadIdx.x;
    const int nl   = tid >> 4;        // node within block
    const int q    = tid & 15;        // batch-quad: handles b = 4q..4q+3
    const int node = blockIdx.x * NPB + nl;
    NodeW& nw = sw[nl];
    const u64 pol_keep   = mk_evict_last_policy();   // x0T + weights: reused x10
    const u64 pol_stream = mk_evict_first_policy();  // ping-pong src: dead after read

    // Issue the gather first (longest latency), overlap with weight staging.
    const int4 c0 = ((const int4*)(in_ixs + (size_t)node * 8))[0];
    const int4 c1 = ((const int4*)(in_ixs + (size_t)node * 8))[1];
    const int cols[8] = {c0.x, c0.y, c0.z, c0.w, c1.x, c1.y, c1.z, c1.w};
    float4 g[8];
#pragma unroll
    for (int d = 0; d < 8; d++)
        g[d] = ld_pol128(src + (((size_t)cols[d]) << 6) + (q << 2), pol_stream);

    // Stage weights (evict_last policy: reused by all 10 layers, pin in L2).
    {
        const float* gW1 = W1 + (size_t)node * 128;
        ((float4*)nw.w1)[q * 2]     = ld_pol128(gW1 + q * 8, pol_keep);
        ((float4*)nw.w1)[q * 2 + 1] = ld_pol128(gW1 + q * 8 + 4, pol_keep);
        const float* gW2 = W2 + (size_t)node * 128;   // [d][j]
#pragma unroll
        for (int d = 0; d < 8; d++)
            nw.w2t[q * 8 + d] = ld_pol32(gW2 + d * 16 + q, pol_keep);  // w2t[j=q][d]
        float bj = ld_pol32(b1 + (size_t)node * 16 + q, pol_keep);
        nw.sb1[q] = pack2(bj, bj);
        if (q < 8) {
            float bd = ld_pol32(b2 + (size_t)node * 8 + q, pol_keep);
            nw.sb2[q] = pack2(bd, bd);
        }
    }
    __syncthreads();

    // Gathered values as packed batch-pairs.
    u64 g0[8], g1[8];
#pragma unroll
    for (int d = 0; d < 8; d++) {
        g0[d] = pack2(g[d].x, g[d].y);
        g1[d] = pack2(g[d].z, g[d].w);
    }

    // Output accumulators (8 out dims x 4 batches), init with b2 splats.
    u64 o0[8], o1[8];
#pragma unroll
    for (int d = 0; d < 8; d++) { o0[d] = nw.sb2[d]; o1[d] = o0[d]; }

#pragma unroll
    for (int j = 0; j < 16; j++) {
        // W1 row j: 8 weights via 2x LDS.128, splat to pairs (ALU movs).
        const float4 wA = ((const float4*)(nw.w1 + j * 8))[0];
        const float4 wB = ((const float4*)(nw.w1 + j * 8))[1];
        u64 s[8];
        s[0] = pack2(wA.x, wA.x); s[1] = pack2(wA.y, wA.y);
        s[2] = pack2(wA.z, wA.z); s[3] = pack2(wA.w, wA.w);
        s[4] = pack2(wB.x, wB.x); s[5] = pack2(wB.y, wB.y);
        s[6] = pack2(wB.z, wB.z); s[7] = pack2(wB.w, wB.w);

        // Two 4-deep chains per batch pair, then combine.
        u64 pA = nw.sb1[j], pB = 0, pC = pA, pD = 0;
#pragma unroll
        for (int d = 0; d < 4; d++) {
            fma2(pA, g0[d], s[d], pA);
            fma2(pB, g0[d + 4], s[d + 4], pB);
            fma2(pC, g1[d], s[d], pC);
            fma2(pD, g1[d + 4], s[d + 4], pD);
        }
        u64 a0 = add2(pA, pB);
        u64 a1 = add2(pC, pD);

        float h0, h1, h2, h3;
        unpack2(a0, h0, h1);
        unpack2(a1, h2, h3);
        h0 = elu1(h0); h1 = elu1(h1); h2 = elu1(h2); h3 = elu1(h3);
        const u64 hh0 = pack2(h0, h1);
        const u64 hh1 = pack2(h2, h3);

        // W2 column j (transposed in smem): 2x LDS.128 + splats.
        const float4 vA = ((const float4*)(nw.w2t + j * 8))[0];
        const float4 vB = ((const float4*)(nw.w2t + j * 8))[1];
        u64 t[8];
        t[0] = pack2(vA.x, vA.x); t[1] = pack2(vA.y, vA.y);
        t[2] = pack2(vA.z, vA.z); t[3] = pack2(vA.w, vA.w);
        t[4] = pack2(vB.x, vB.x); t[5] = pack2(vB.y, vB.y);
        t[6] = pack2(vB.z, vB.z); t[7] = pack2(vB.w, vB.w);
#pragma unroll
        for (int d = 0; d < 8; d++) {
            fma2(o0[d], hh0, t[d], o0[d]);
            fma2(o1[d], hh1, t[d], o1[d]);
        }
    }

    if (!final_flag) {
        // Residual (x0T pinned) + DEFAULT store: next layer reads dst.
#pragma unroll
        for (int d = 0; d < 8; d++) {
            const size_t col = (size_t)node * 8 + d;
            const float4 r = ld_pol128(x0T + (col << 6) + (q << 2), pol_keep);
            float a, bb, c, dd;
            unpack2(o0[d], a, bb);
            unpack2(o1[d], c, dd);
            *(float4*)(dst + (col << 6) + (q << 2)) =
                make_float4(a + r.x, bb + r.y, c + r.z, dd + r.w);
        }
    } else {
        // Residual + register transpose + direct (B,E) output store.
        float ob[4][8];
#pragma unroll
        for (int d = 0; d < 8; d++) {
            const size_t col = (size_t)node * 8 + d;
            const float4 r = ld_pol128(x0T + (col << 6) + (q << 2), pol_keep);
            float a, bb, c, dd;
            unpack2(o0[d], a, bb);
            unpack2(o1[d], c, dd);
            ob[0][d] = a + r.x; ob[1][d] = bb + r.y;
            ob[2][d] = c + r.z; ob[3][d] = dd + r.w;
        }
#pragma unroll
        for (int rr = 0; rr < 4; rr++) {
            float* p = dst + (size_t)(q * 4 + rr) * E + (size_t)node * 8;
            *(float4*)(p)     = make_float4(ob[rr][0], ob[rr][1], ob[rr][2], ob[rr][3]);
            *(float4*)(p + 4) = make_float4(ob[rr][4], ob[rr][5], ob[rr][6], ob[rr][7]);
        }
    }
}

extern "C" void kernel_launch(void* const* d_in, const int* in_sizes, int n_in,
                              void* d_out, int out_size) {
    const float* x0     = (const float*)d_in[0];
    const float* W1     = (const float*)d_in[1];
    const float* b1     = (const float*)d_in[2];
    const float* W2     = (const float*)d_in[3];
    const float* b2     = (const float*)d_in[4];
    const int*   in_ixs = (const int*)d_in[5];
    float* out = (float*)d_out;

    float *x0T, *xA, *xB;
    cudaGetSymbolAddress((void**)&x0T, g_x0T);
    cudaGetSymbolAddress((void**)&xA,  g_xA);
    cudaGetSymbolAddress((void**)&xB,  g_xB);

    k_transpose_in<<<dim3(E / 32, B / 32), dim3(32, 32)>>>(x0, x0T);

    const float* src = x0T;
    float* bufs[2] = {xA, xB};
    for (int L = 0; L < LAYERS; L++) {
        const int fin = (L == LAYERS - 1);
        float* dst = fin ? out : bufs[L & 1];
        layer_kernel<<<F_NODES / NPB, NPB * TPN>>>(src, dst, W1, b1, W2, b2,
                                                   in_ixs, x0T, fin);
        src = dst;
    }
}

// round 9
// speedup vs baseline: 1.6344x; 1.6344x over previous
#include <cuda_runtime.h>
#include <cuda_fp16.h>

#define F_NODES 16384
#define DEG 8
#define E (F_NODES * DEG)   // 131072
#define B 64
#define H 16
#define LAYERS 10

#define NPB 8               // nodes per block
#define TPN 16              // threads per node (4 batch elems each)

typedef unsigned long long u64;

// x0 kept fp32 (exact residual); layer-to-layer x stored fp16 so the whole
// working set (~86MB) fits L2 naturally (no policy hints -- they regressed).
__device__ float  g_x0T[(size_t)E * B];
__device__ __half g_x0H[(size_t)E * B];
__device__ __half g_hA [(size_t)E * B];
__device__ __half g_hB [(size_t)E * B];

__device__ __forceinline__ u64 pack2(float lo, float hi) {
    u64 r; asm("mov.b64 %0, {%1, %2};" : "=l"(r) : "f"(lo), "f"(hi)); return r;
}
__device__ __forceinline__ void unpack2(u64 v, float& lo, float& hi) {
    asm("mov.b64 {%0, %1}, %2;" : "=f"(lo), "=f"(hi) : "l"(v));
}
__device__ __forceinline__ void fma2(u64& d, u64 a, u64 b, u64 c) {
    asm("fma.rn.f32x2 %0, %1, %2, %3;" : "=l"(d) : "l"(a), "l"(b), "l"(c));
}
__device__ __forceinline__ u64 add2(u64 a, u64 b) {
    u64 r; asm("add.rn.f32x2 %0, %1, %2;" : "=l"(r) : "l"(a), "l"(b)); return r;
}
// ELU via select: 5 ops (FMUL+MUFU+FADD+FSETP+FSEL), no branch.
// exp overflow for large +x is discarded by the select.
__device__ __forceinline__ float elu1(float x) {
    float e = __expf(x) - 1.0f;
    return x > 0.0f ? x : e;
}

// Per-node smem weights.
struct __align__(16) NodeW {
    u64   sb1[16];     // b1 splats (bj, bj)
    u64   sb2p[4];     // b2 pairs (b2[2k], b2[2k+1]) -- raw order
    float w1[128];     // W1[j][d], j-major (raw global layout)
    float w2t[128];    // W2 column-major: w2t[j*8 + d] = W2[d][j]
    u64   pad[2];
};

// (B, E) row-major -> (E, B) fp32 (residual source) + fp16 (layer-0 input)
__global__ void k_transpose_in(const float* __restrict__ in,
                               float* __restrict__ outf, __half* __restrict__ outh) {
    __shared__ float t[32][33];
    int e0 = blockIdx.x * 32, b0 = blockIdx.y * 32;
    int tx = threadIdx.x, ty = threadIdx.y;
    t[ty][tx] = in[(size_t)(b0 + ty) * E + e0 + tx];
    __syncthreads();
    float v = t[tx][ty];
    size_t o = (size_t)(e0 + ty) * B + b0 + tx;
    outf[o] = v;
    outh[o] = __float2half(v);
}

// One GSNN layer in (E, B) space. 16 threads/node, 4 batch elems/thread.
// Math fp32; x read/written fp16 except the final layer which writes fp32
// (B, E) directly (register transpose).
__global__ __launch_bounds__(NPB * TPN)
void layer_kernel(const __half* __restrict__ src, __half* __restrict__ dsth,
                  float* __restrict__ dstf,
                  const float* __restrict__ W1, const float* __restrict__ b1,
                  const float* __restrict__ W2, const float* __restrict__ b2,
                  const int* __restrict__ in_ixs, const float* __restrict__ x0T,
                  int final_flag) {
    __shared__ NodeW sw[NPB];
    const int tid  = threadIdx.x;
    const int nl   = tid >> 4;        // node within block
    const int q    = tid & 15;        // batch-quad: handles b = 4q..4q+3
    const int node = blockIdx.x * NPB + nl;
    NodeW& nw = sw[nl];

    // Issue gathers first (longest latency); 8B (4 halves) per thread per column.
    const int4 c0 = ((const int4*)(in_ixs + (size_t)node * 8))[0];
    const int4 c1 = ((const int4*)(in_ixs + (size_t)node * 8))[1];
    const int cols[8] = {c0.x, c0.y, c0.z, c0.w, c1.x, c1.y, c1.z, c1.w};
    uint2 gh[8];
#pragma unroll
    for (int d = 0; d < 8; d++)
        gh[d] = *(const uint2*)(src + (((size_t)cols[d]) << 6) + (q << 2));

    // Stage weights (plain loads).
    {
        const float4* gW1 = (const float4*)(W1 + (size_t)node * 128);
        ((float4*)nw.w1)[q * 2]     = gW1[q * 2];
        ((float4*)nw.w1)[q * 2 + 1] = gW1[q * 2 + 1];
        const float* gW2 = W2 + (size_t)node * 128;   // [d][j]
#pragma unroll
        for (int d = 0; d < 8; d++)
            nw.w2t[q * 8 + d] = gW2[d * 16 + q];      // w2t[j=q][d]
        float bj = b1[(size_t)node * 16 + q];
        nw.sb1[q] = pack2(bj, bj);
        if (q < 4)
            nw.sb2p[q] = *(const u64*)(b2 + (size_t)node * 8 + q * 2);
    }
    __syncthreads();

    // Convert gathered halves to packed fp32 batch-pairs.
    u64 g0[8], g1[8];
#pragma unroll
    for (int d = 0; d < 8; d++) {
        __half2 ha = *(__half2*)&gh[d].x;
        __half2 hb = *(__half2*)&gh[d].y;
        g0[d] = pack2(__low2float(ha), __high2float(ha));
        g1[d] = pack2(__low2float(hb), __high2float(hb));
    }

    // Output accumulators o[k][b]: lanes = out-dim pair (2k, 2k+1), per batch b.
    u64 o[4][4];
#pragma unroll
    for (int k = 0; k < 4; k++) {
        const u64 bp = nw.sb2p[k];
        o[k][0] = bp; o[k][1] = bp; o[k][2] = bp; o[k][3] = bp;
    }

#pragma unroll
    for (int j = 0; j < 16; j++) {
        // W1 row j: 8 weights via 2x LDS.128, splat to pairs.
        const float4 wA = ((const float4*)(nw.w1 + j * 8))[0];
        const float4 wB = ((const float4*)(nw.w1 + j * 8))[1];
        u64 s[8];
        s[0] = pack2(wA.x, wA.x); s[1] = pack2(wA.y, wA.y);
        s[2] = pack2(wA.z, wA.z); s[3] = pack2(wA.w, wA.w);
        s[4] = pack2(wB.x, wB.x); s[5] = pack2(wB.y, wB.y);
        s[6] = pack2(wB.z, wB.z); s[7] = pack2(wB.w, wB.w);

        // Two 4-deep chains per batch pair, then combine.
        u64 pA = nw.sb1[j], pB = 0, pC = pA, pD = 0;
#pragma unroll
        for (int d = 0; d < 4; d++) {
            fma2(pA, g0[d], s[d], pA);
            fma2(pB, g0[d + 4], s[d + 4], pB);
            fma2(pC, g1[d], s[d], pC);
            fma2(pD, g1[d + 4], s[d + 4], pD);
        }
        u64 a0 = add2(pA, pB);
        u64 a1 = add2(pC, pD);

        float h0, h1, h2, h3;
        unpack2(a0, h0, h1);
        unpack2(a1, h2, h3);
        h0 = elu1(h0); h1 = elu1(h1); h2 = elu1(h2); h3 = elu1(h3);
        const u64 hs0 = pack2(h0, h0), hs1 = pack2(h1, h1);
        const u64 hs2 = pack2(h2, h2), hs3 = pack2(h3, h3);

        // W2 column j consumed as packed d-pairs straight from LDS.128 (no splats).
        const float4 vA = ((const float4*)(nw.w2t + j * 8))[0];
        const float4 vB = ((const float4*)(nw.w2t + j * 8))[1];
        const u64 w2q0 = pack2(vA.x, vA.y), w2q1 = pack2(vA.z, vA.w);
        const u64 w2q2 = pack2(vB.x, vB.y), w2q3 = pack2(vB.z, vB.w);
        fma2(o[0][0], hs0, w2q0, o[0][0]); fma2(o[0][1], hs1, w2q0, o[0][1]);
        fma2(o[0][2], hs2, w2q0, o[0][2]); fma2(o[0][3], hs3, w2q0, o[0][3]);
        fma2(o[1][0], hs0, w2q1, o[1][0]); fma2(o[1][1], hs1, w2q1, o[1][1]);
        fma2(o[1][2], hs2, w2q1, o[1][2]); fma2(o[1][3], hs3, w2q1, o[1][3]);
        fma2(o[2][0], hs0, w2q2, o[2][0]); fma2(o[2][1], hs1, w2q2, o[2][1]);
        fma2(o[2][2], hs2, w2q2, o[2][2]); fma2(o[2][3], hs3, w2q2, o[2][3]);
        fma2(o[3][0], hs0, w2q3, o[3][0]); fma2(o[3][1], hs1, w2q3, o[3][1]);
        fma2(o[3][2], hs2, w2q3, o[3][2]); fma2(o[3][3], hs3, w2q3, o[3][3]);
    }

    // Extract out[d][b] scalars (lane extracts are register aliases).
    float ov[8][4];
#pragma unroll
    for (int k = 0; k < 4; k++)
#pragma unroll
        for (int b = 0; b < 4; b++) {
            float lo, hi;
            unpack2(o[k][b], lo, hi);
            ov[2 * k][b]     = lo;
            ov[2 * k + 1][b] = hi;
        }

    if (!final_flag) {
        // Residual (fp32) + fp16 store to (E,B) ping-pong.
#pragma unroll
        for (int d = 0; d < 8; d++) {
            const size_t col = (size_t)node * 8 + d;
            const float4 r = *(const float4*)(x0T + (col << 6) + (q << 2));
            __half2 ha = __floats2half2_rn(ov[d][0] + r.x, ov[d][1] + r.y);
            __half2 hb = __floats2half2_rn(ov[d][2] + r.z, ov[d][3] + r.w);
            uint2 st; st.x = *(unsigned*)&ha; st.y = *(unsigned*)&hb;
            *(uint2*)(dsth + (col << 6) + (q << 2)) = st;
        }
    } else {
        // Residual + register transpose + direct fp32 (B,E) output store.
        float ob[4][8];
#pragma unroll
        for (int d = 0; d < 8; d++) {
            const size_t col = (size_t)node * 8 + d;
            const float4 r = *(const float4*)(x0T + (col << 6) + (q << 2));
            ob[0][d] = ov[d][0] + r.x; ob[1][d] = ov[d][1] + r.y;
            ob[2][d] = ov[d][2] + r.z; ob[3][d] = ov[d][3] + r.w;
        }
#pragma unroll
        for (int rr = 0; rr < 4; rr++) {
            float* p = dstf + (size_t)(q * 4 + rr) * E + (size_t)node * 8;
            *(float4*)(p)     = make_float4(ob[rr][0], ob[rr][1], ob[rr][2], ob[rr][3]);
            *(float4*)(p + 4) = make_float4(ob[rr][4], ob[rr][5], ob[rr][6], ob[rr][7]);
        }
    }
}

extern "C" void kernel_launch(void* const* d_in, const int* in_sizes, int n_in,
                              void* d_out, int out_size) {
    const float* x0     = (const float*)d_in[0];
    const float* W1     = (const float*)d_in[1];
    const float* b1     = (const float*)d_in[2];
    const float* W2     = (const float*)d_in[3];
    const float* b2     = (const float*)d_in[4];
    const int*   in_ixs = (const int*)d_in[5];
    float* out = (float*)d_out;

    float *x0T;
    __half *x0H, *hA, *hB;
    cudaGetSymbolAddress((void**)&x0T, g_x0T);
    cudaGetSymbolAddress((void**)&x0H, g_x0H);
    cudaGetSymbolAddress((void**)&hA,  g_hA);
    cudaGetSymbolAddress((void**)&hB,  g_hB);

    k_transpose_in<<<dim3(E / 32, B / 32), dim3(32, 32)>>>(x0, x0T, x0H);

    const __half* src = x0H;
    __half* bufs[2] = {hA, hB};
    for (int L = 0; L < LAYERS; L++) {
        const int fin = (L == LAYERS - 1);
        __half* dh = fin ? nullptr : bufs[L & 1];
        layer_kernel<<<F_NODES / NPB, NPB * TPN>>>(src, dh, fin ? out : nullptr,
                                                   W1, b1, W2, b2, in_ixs, x0T, fin);
        src = dh;
    }
}